// round 1
// baseline (speedup 1.0000x reference)
#include <cuda_runtime.h>
#include <cstdint>

// Problem constants
#define BB 48
#define LL 128
#define DD 1024
#define HH 150      // ffnn out
#define HP 151      // +bias col
#define OO 9
#define LDX 160     // padded feature stride (cols 151..159 zero)

#define N_CELLS (LL*LL)              // 16384
#define SCORE_ELEMS (BB*LL*LL*OO)    // 7077888
#define RESULT_ELEMS (BB*LL*LL)      // 786432

// ---------------- static device scratch (no runtime allocation allowed) ------
__device__ float Xg[(size_t)BB*LL*LDX];               // [6144][160], col150=1, 151..159=0
__device__ float Yg[(size_t)BB*LL*LDX];
__device__ float Tg[(size_t)BB*OO*LL*LDX];            // [(b*9+o)][128][160]
__device__ float Sg[(size_t)SCORE_ELEMS];             // fallback score buffer

// ---------------- f32x2 helpers ---------------------------------------------
__device__ __forceinline__ void fma2(unsigned long long& d, unsigned long long a,
                                     unsigned long long b) {
    asm("fma.rn.f32x2 %0, %1, %2, %0;" : "+l"(d) : "l"(a), "l"(b));
}
__device__ __forceinline__ unsigned long long pack2(float x) {
    unsigned long long r;
    asm("mov.b64 %0, {%1, %1};" : "=l"(r) : "f"(x));
    return r;
}
__device__ __forceinline__ float2 unpack2(unsigned long long v) {
    float2 f;
    asm("mov.b64 {%0, %1}, %2;" : "=f"(f.x), "=f"(f.y) : "l"(v));
    return f;
}

// 8-row x 8-col (4 f32x2) micro step
__device__ __forceinline__ void micro_step(const float* __restrict__ aRow,
                                           const float* __restrict__ bRow,
                                           unsigned long long acc[8][4]) {
    float4 a0 = *(const float4*)(aRow);
    float4 a1 = *(const float4*)(aRow + 4);
    ulonglong2 q0 = *(const ulonglong2*)(bRow);
    ulonglong2 q1 = *(const ulonglong2*)(bRow + 4);
    unsigned long long bb[4] = {q0.x, q0.y, q1.x, q1.y};
    float av[8] = {a0.x, a0.y, a0.z, a0.w, a1.x, a1.y, a1.z, a1.w};
#pragma unroll
    for (int r = 0; r < 8; r++) {
        unsigned long long ap = pack2(av[r]);
#pragma unroll
        for (int p = 0; p < 4; p++) fma2(acc[r][p], ap, bb[p]);
    }
}

// ============================================================================
// Kernel 1: projections.  X/Y[r][c] = bert[r]·w[c] + bias[c]; col150=1; pad=0
// grid (48, 2): blockIdx.x = 128-row tile, blockIdx.y = 0(start/X) 1(end/Y)
// block 320 = 16(ty, rows) x 20(tx, col-octets)
// ============================================================================
__global__ __launch_bounds__(320) void proj_kernel(
    const float* __restrict__ bert,
    const float* __restrict__ wS, const float* __restrict__ bS,
    const float* __restrict__ wE, const float* __restrict__ bE) {
    const int z = blockIdx.y;
    const float* w    = z ? wE : wS;
    const float* bias = z ? bE : bS;
    float* outp       = z ? Yg : Xg;
    const int mBase = blockIdx.x * 128;

    __shared__ alignas(16) float As[16][132];
    __shared__ alignas(16) float Bs[16][164];

    const int t = threadIdx.x;
    const int tx = t % 20, ty = t / 20;

    unsigned long long acc[8][4];
#pragma unroll
    for (int r = 0; r < 8; r++)
#pragma unroll
        for (int p = 0; p < 4; p++) acc[r][p] = 0ull;

    for (int k0 = 0; k0 < DD; k0 += 16) {
        for (int e = t; e < 128 * 16; e += 320) {
            int row = e >> 4, kk = e & 15;
            As[kk][row] = bert[(size_t)(mBase + row) * DD + k0 + kk];
        }
        for (int e = t; e < 160 * 16; e += 320) {
            int c = e >> 4, kk = e & 15;
            Bs[kk][c] = (c < HH) ? w[(size_t)c * DD + k0 + kk] : 0.f;
        }
        __syncthreads();
#pragma unroll
        for (int kk = 0; kk < 16; kk++)
            micro_step(&As[kk][ty * 8], &Bs[kk][tx * 8], acc);
        __syncthreads();
    }

#pragma unroll
    for (int r = 0; r < 8; r++) {
        int row = mBase + ty * 8 + r;
        float* orow = &outp[(size_t)row * LDX];
#pragma unroll
        for (int p = 0; p < 4; p++) {
            float2 v = unpack2(acc[r][p]);
            int c0 = tx * 8 + 2 * p;
            float o0 = (c0 < HH) ? v.x + bias[c0] : (c0 == HH ? 1.f : 0.f);
            int c1 = c0 + 1;
            float o1 = (c1 < HH) ? v.y + bias[c1] : (c1 == HH ? 1.f : 0.f);
            orow[c0] = o0;
            orow[c1] = o1;
        }
    }
}

// ============================================================================
// Kernel 2: T[(b,o)][x][j] = sum_i X[b][x][i] * W[o][i][j]    (K=160, pads 0)
// grid 432 (= b*9+o), block 320
// ============================================================================
__global__ __launch_bounds__(320) void biaff_left(const float* __restrict__ Wb) {
    const int blk = blockIdx.x;
    const int b = blk / OO, o = blk % OO;
    const float* Xb = &Xg[(size_t)b * LL * LDX];
    const float* Wo = Wb + (size_t)o * HP * HP;
    float* Tp = &Tg[(size_t)blk * LL * LDX];

    __shared__ alignas(16) float As[16][132];
    __shared__ alignas(16) float Bs[16][164];

    const int t = threadIdx.x;
    const int tx = t % 20, ty = t / 20;

    unsigned long long acc[8][4];
#pragma unroll
    for (int r = 0; r < 8; r++)
#pragma unroll
        for (int p = 0; p < 4; p++) acc[r][p] = 0ull;

    for (int k0 = 0; k0 < LDX; k0 += 16) {
        for (int e = t; e < 128 * 16; e += 320) {
            int row = e >> 4, kk = e & 15;
            As[kk][row] = Xb[(size_t)row * LDX + k0 + kk];
        }
        for (int e = t; e < 160 * 16; e += 320) {
            int kk = e / 160, j = e % 160;
            int i = k0 + kk;
            Bs[kk][j] = (i < HP && j < HP) ? Wo[(size_t)i * HP + j] : 0.f;
        }
        __syncthreads();
#pragma unroll
        for (int kk = 0; kk < 16; kk++)
            micro_step(&As[kk][ty * 8], &Bs[kk][tx * 8], acc);
        __syncthreads();
    }

#pragma unroll
    for (int r = 0; r < 8; r++) {
        float* orow = &Tp[(size_t)(ty * 8 + r) * LDX];
#pragma unroll
        for (int p = 0; p < 4; p++) {
            float2 v = unpack2(acc[r][p]);
            int c0 = tx * 8 + 2 * p;
            orow[c0] = v.x;
            orow[c0 + 1] = v.y;
        }
    }
}

// ============================================================================
// Kernel 3: score[b][x][y][o] = sum_j T[(b,o)][x][j] * Y[b][y][j]
// grid 432, block 256 = 16x16
// ============================================================================
__global__ __launch_bounds__(256) void biaff_right(float* __restrict__ outp) {
    const int blk = blockIdx.x;
    const int b = blk / OO, o = blk % OO;
    const float* Tp = &Tg[(size_t)blk * LL * LDX];
    const float* Yb = &Yg[(size_t)b * LL * LDX];

    __shared__ alignas(16) float As[16][132];
    __shared__ alignas(16) float Bs[16][132];

    const int t = threadIdx.x;
    const int tx = t % 16, ty = t / 16;

    unsigned long long acc[8][4];
#pragma unroll
    for (int r = 0; r < 8; r++)
#pragma unroll
        for (int p = 0; p < 4; p++) acc[r][p] = 0ull;

    for (int k0 = 0; k0 < LDX; k0 += 16) {
        for (int e = t; e < 128 * 16; e += 256) {
            int row = e >> 4, kk = e & 15;
            As[kk][row] = Tp[(size_t)row * LDX + k0 + kk];
        }
        for (int e = t; e < 128 * 16; e += 256) {
            int row = e >> 4, kk = e & 15;
            Bs[kk][row] = Yb[(size_t)row * LDX + k0 + kk];
        }
        __syncthreads();
#pragma unroll
        for (int kk = 0; kk < 16; kk++)
            micro_step(&As[kk][ty * 8], &Bs[kk][tx * 8], acc);
        __syncthreads();
    }

#pragma unroll
    for (int r = 0; r < 8; r++) {
        int x = ty * 8 + r;
        size_t base = ((size_t)(b * LL + x) * LL) * OO + o;
#pragma unroll
        for (int p = 0; p < 4; p++) {
            float2 v = unpack2(acc[r][p]);
            int y0 = tx * 8 + 2 * p;
            outp[base + (size_t)y0 * OO] = v.x;
            outp[base + (size_t)(y0 + 1) * OO] = v.y;
        }
    }
}

// ============================================================================
// Kernel 4: per-sentence greedy decode.
// grid 48, block 1024, dyn smem = 16384*8 (keys) + 16384 (argmax bytes)
// ============================================================================
__device__ __forceinline__ unsigned long long rmask64(int lo, int hi) {
    unsigned long long m = (hi >= 63) ? ~0ull : ((1ull << (hi + 1)) - 1ull);
    return m & (~0ull << lo);
}

__global__ __launch_bounds__(1024) void decode_kernel(
    const float* __restrict__ score,
    const int* __restrict__ tagseq,
    float* __restrict__ resOut) {
    const int b = blockIdx.x;
    const int tid = threadIdx.x;

    extern __shared__ unsigned long long smdyn[];
    unsigned long long* keys = smdyn;                       // 16384 u64
    unsigned char* ansS = (unsigned char*)(smdyn + N_CELLS); // 16384 u8

    const float* sB = score + (size_t)b * N_CELLS * OO;
    const int* mB = tagseq + (size_t)b * N_CELLS;
    float* rB = resOut + (size_t)b * N_CELLS;

    // Phase 1: argmax over O, validity, packed sort keys, result init
    for (int idx = tid; idx < N_CELLS; idx += blockDim.x) {
        const float* sp = sB + (size_t)idx * OO;
        float best = sp[0];
        int bo = 0;
#pragma unroll
        for (int o = 1; o < OO; o++) {
            float v = sp[o];
            if (v > best) { best = v; bo = o; }
        }
        ansS[idx] = (unsigned char)bo;
        bool valid = (bo != 1) && (mB[idx] > 0);
        unsigned u = __float_as_uint(best);
        u ^= (u & 0x80000000u) ? 0xFFFFFFFFu : 0x80000000u;  // ascending-orderable
        unsigned ud = ~u;                                    // descending-orderable
        if (!valid) ud = 0xFFFFFFFFu;
        keys[idx] = ((unsigned long long)ud << 32) | (unsigned)idx;
        rB[idx] = 1.0f;  // NON_ENTITY
    }
    __syncthreads();

    // Phase 2: bitonic sort ascending (desc score, ties row-major)
    for (unsigned k = 2; k <= (unsigned)N_CELLS; k <<= 1) {
        for (unsigned j = k >> 1; j > 0; j >>= 1) {
            for (unsigned e = tid; e < (unsigned)N_CELLS; e += blockDim.x) {
                unsigned ixj = e ^ j;
                if (ixj > e) {
                    unsigned long long a = keys[e], c = keys[ixj];
                    bool up = (e & k) == 0;
                    if ((a > c) == up) { keys[e] = c; keys[ixj] = a; }
                }
            }
            __syncthreads();
        }
    }

    // Phase 3: warp 0 speculative-window greedy scan
    if (tid < 32) {
        const unsigned FULL = 0xFFFFFFFFu;
        unsigned long long st0 = 0, st1 = 0, cv0 = 0, cv1 = 0;
        int t = 0;
        while (t < N_CELLS) {
            int my = t + tid;
            unsigned long long kk = (my < N_CELLS) ? keys[my]
                                                   : 0xFFFFFFFF00000000ull;
            unsigned ud = (unsigned)(kk >> 32);
            bool isval = (ud != 0xFFFFFFFFu);
            int idx = (int)(unsigned)kk;
            int i = idx >> 7, j = idx & 127;

            bool upper = (j >= i);
            unsigned long long sp0 = 0, sp1 = 0;
            if (upper) {
                if (i <= 63) sp0 = rmask64(i, j < 63 ? j : 63);
                if (j >= 64) sp1 = rmask64(i > 64 ? i - 64 : 0, j - 64);
            }
            bool stbit = (i < 64) ? ((st0 >> i) & 1ull) : ((st1 >> (i - 64)) & 1ull);
            bool cvbit = (i < 64) ? ((cv0 >> i) & 1ull) : ((cv1 >> (i - 64)) & 1ull);
            bool conflict = (((st0 & sp0) | (st1 & sp1)) != 0ull) || cvbit;
            bool acc = isval && !conflict;
            bool schg = acc && (upper || !stbit);

            unsigned bInv = __ballot_sync(FULL, !isval);
            int fI = bInv ? (__ffs(bInv) - 1) : 32;
            unsigned bS = __ballot_sync(FULL, schg);
            if (fI < 32) bS &= (fI ? ((1u << fI) - 1u) : 0u);
            int fS = bS ? (__ffs(bS) - 1) : 32;
            int lim = fS < fI ? fS : fI;

            // finalized plain accepts (no state change) before first changer
            if (acc && (int)tid < lim) rB[idx] = (float)ansS[idx];

            if (fS < fI && fS < 32) {
                if ((int)tid == fS) {
                    rB[idx] = (float)ansS[idx];
                    if (i < 64) st0 |= (1ull << i); else st1 |= (1ull << (i - 64));
                    if (upper) { cv0 |= sp0; cv1 |= sp1; }
                }
                st0 = __shfl_sync(FULL, st0, fS);
                st1 = __shfl_sync(FULL, st1, fS);
                cv0 = __shfl_sync(FULL, cv0, fS);
                cv1 = __shfl_sync(FULL, cv1, fS);
                t += fS + 1;
            } else if (fI < 32) {
                break;  // sorted invalid tail reached
            } else {
                t += 32;
            }
        }
    }
}

// ============================================================================
extern "C" void kernel_launch(void* const* d_in, const int* in_sizes, int n_in,
                              void* d_out, int out_size) {
    (void)in_sizes; (void)n_in;
    const float* bert = (const float*)d_in[0];
    const int*   tagseq = (const int*)d_in[1];
    const float* wS = (const float*)d_in[2];
    const float* bS = (const float*)d_in[3];
    const float* wE = (const float*)d_in[4];
    const float* bE = (const float*)d_in[5];
    const float* Wb = (const float*)d_in[6];
    float* out = (float*)d_out;

    bool scoreInOut = (out_size >= SCORE_ELEMS);
    float* scorePtr = out;
    if (!scoreInOut) {
        void* p = nullptr;
        cudaGetSymbolAddress(&p, Sg);
        scorePtr = (float*)p;
    }

    proj_kernel<<<dim3(48, 2), 320>>>(bert, wS, bS, wE, bE);
    biaff_left<<<432, 320>>>(Wb);
    biaff_right<<<432, 256>>>(scorePtr);

    float* resPtr = nullptr;
    if (out_size >= SCORE_ELEMS + RESULT_ELEMS) resPtr = out + SCORE_ELEMS;
    else if (!scoreInOut && out_size >= RESULT_ELEMS) resPtr = out;

    if (resPtr) {
        const int dynsmem = N_CELLS * 8 + N_CELLS;  // keys + ans bytes
        cudaFuncSetAttribute(decode_kernel,
                             cudaFuncAttributeMaxDynamicSharedMemorySize, dynsmem);
        decode_kernel<<<48, 1024, dynsmem>>>(scorePtr, tagseq, resPtr);
    }
}